// round 2
// baseline (speedup 1.0000x reference)
#include <cuda_runtime.h>
#include <math.h>

#define BB 4
#define TT 2048
#define CC 768
#define HH 12
#define DH 64
#define NN (BB*TT)   // 8192 rows

// Scratch (static device memory; allocation APIs are banned)
__device__ float g_q[BB*HH*TT*DH];
__device__ float g_k[BB*HH*TT*DH];
__device__ float g_v[BB*HH*TT*DH];
__device__ float g_y[NN*CC];

#define NEG_INF (-1.0e30f)

// ---------------------------------------------------------------------------
// NT GEMM: out[n,o] = sum_c A[n,c] * W[o,c] + bias[o]
// A: [NN, CC] row-major.  W: [CC, CC] row-major (torch Linear weight).
// SPLIT=true : write to head-split layout [B, H, T, DH] (for Q/K/V)
// SPLIT=false: write to [NN, CC] (final projection / d_out)
// Tile: BM=BN=64, BK=16. 256 threads, 4x4 register tile per thread.
// ---------------------------------------------------------------------------
template<bool SPLIT>
__global__ void __launch_bounds__(256)
gemm_nt(const float* __restrict__ A, const float* __restrict__ W,
        const float* __restrict__ bias, float* __restrict__ out) {
    __shared__ float As[16][68];   // [k][row], pad 68 keeps float4 alignment
    __shared__ float Ws[16][68];

    const int tx = threadIdx.x, ty = threadIdx.y;
    const int tid = ty * 16 + tx;
    const int n0 = blockIdx.x * 64;
    const int o0 = blockIdx.y * 64;

    const int lc = tid & 15;     // k within tile (fast index -> coalesced LDG)
    const int lr = tid >> 4;     // row base

    float acc[4][4];
    #pragma unroll
    for (int i = 0; i < 4; i++)
        #pragma unroll
        for (int j = 0; j < 4; j++) acc[i][j] = 0.f;

    for (int k0 = 0; k0 < CC; k0 += 16) {
        #pragma unroll
        for (int l = 0; l < 4; l++) {
            int r = lr + l * 16;
            As[lc][r] = A[(size_t)(n0 + r) * CC + k0 + lc];
            Ws[lc][r] = W[(size_t)(o0 + r) * CC + k0 + lc];
        }
        __syncthreads();
        #pragma unroll
        for (int k = 0; k < 16; k++) {
            float4 a4 = *(const float4*)&As[k][ty * 4];
            float4 b4 = *(const float4*)&Ws[k][tx * 4];
            float av[4] = {a4.x, a4.y, a4.z, a4.w};
            float bv[4] = {b4.x, b4.y, b4.z, b4.w};
            #pragma unroll
            for (int i = 0; i < 4; i++)
                #pragma unroll
                for (int j = 0; j < 4; j++)
                    acc[i][j] += av[i] * bv[j];
        }
        __syncthreads();
    }

    #pragma unroll
    for (int i = 0; i < 4; i++) {
        int n = n0 + ty * 4 + i;
        #pragma unroll
        for (int j = 0; j < 4; j++) {
            int o = o0 + tx * 4 + j;
            float v = acc[i][j] + bias[o];
            if (SPLIT) {
                int b = n >> 11;          // n / TT
                int t = n & (TT - 1);
                int h = o >> 6;           // o / DH
                int d = o & (DH - 1);
                out[(((size_t)b * HH + h) * TT + t) * DH + d] = v;
            } else {
                out[(size_t)n * CC + o] = v;
            }
        }
    }
}

// ---------------------------------------------------------------------------
// Flash attention, fp32, causal. One block per (q-tile of 64, b*h).
// Br=Bc=64, Dh=64. Online softmax. Block 16x16 threads, 4x4 register tiles.
// Shared: Qs[64][65], KPs[64][65] (K tile, reused for P), Vs[64][65].
// ---------------------------------------------------------------------------
__global__ void __launch_bounds__(256)
flash_attn(const float* __restrict__ Q, const float* __restrict__ K,
           const float* __restrict__ V, float* __restrict__ O) {
    extern __shared__ float sm[];
    float* Qs  = sm;                 // 64*65
    float* KPs = sm + 64 * 65;       // K tile, then P tile
    float* Vs  = sm + 2 * 64 * 65;

    const int tx = threadIdx.x, ty = threadIdx.y;
    const int tid = ty * 16 + tx;
    const int bh = blockIdx.y;
    const int b  = bh / HH;
    const int h  = bh - b * HH;
    const int q0 = blockIdx.x * 64;
    const size_t base = (size_t)bh * TT * DH;

    // Load Q tile (coalesced)
    #pragma unroll
    for (int l = 0; l < 16; l++) {
        int id = tid + l * 256;
        int r = id >> 6, c = id & 63;
        Qs[r * 65 + c] = Q[base + (size_t)(q0 + r) * DH + c];
    }

    float m[4], lsum[4], o[4][4];
    #pragma unroll
    for (int i = 0; i < 4; i++) {
        m[i] = NEG_INF; lsum[i] = 0.f;
        #pragma unroll
        for (int j = 0; j < 4; j++) o[i][j] = 0.f;
    }
    const float scale = 0.125f;  // 1/sqrt(64)

    const int ktiles = blockIdx.x + 1;   // causal
    for (int kt = 0; kt < ktiles; kt++) {
        const int k0 = kt * 64;
        #pragma unroll
        for (int l = 0; l < 16; l++) {
            int id = tid + l * 256;
            int r = id >> 6, c = id & 63;
            KPs[r * 65 + c] = K[base + (size_t)(k0 + r) * DH + c];
            Vs[r * 65 + c]  = V[base + (size_t)(k0 + r) * DH + c];
        }
        __syncthreads();

        // S = Q K^T
        float s[4][4];
        #pragma unroll
        for (int i = 0; i < 4; i++)
            #pragma unroll
            for (int j = 0; j < 4; j++) s[i][j] = 0.f;
        #pragma unroll 8
        for (int d = 0; d < 64; d++) {
            float a[4], bv[4];
            #pragma unroll
            for (int i = 0; i < 4; i++) a[i]  = Qs[(ty * 4 + i) * 65 + d];
            #pragma unroll
            for (int j = 0; j < 4; j++) bv[j] = KPs[(tx * 4 + j) * 65 + d];
            #pragma unroll
            for (int i = 0; i < 4; i++)
                #pragma unroll
                for (int j = 0; j < 4; j++)
                    s[i][j] += a[i] * bv[j];
        }

        const bool diag = (kt == blockIdx.x);
        // online softmax update (per q-row, row spread over 16 lanes sharing ty)
        #pragma unroll
        for (int i = 0; i < 4; i++) {
            const int qr = q0 + ty * 4 + i;
            float rmax = NEG_INF;
            #pragma unroll
            for (int j = 0; j < 4; j++) {
                float v = s[i][j] * scale;
                if (diag && (k0 + tx * 4 + j) > qr) v = NEG_INF;
                s[i][j] = v;
                rmax = fmaxf(rmax, v);
            }
            #pragma unroll
            for (int off = 8; off > 0; off >>= 1)
                rmax = fmaxf(rmax, __shfl_xor_sync(0xffffffffu, rmax, off));
            float mn = fmaxf(m[i], rmax);
            float corr = __expf(m[i] - mn);
            m[i] = mn;
            float ps = 0.f;
            #pragma unroll
            for (int j = 0; j < 4; j++) {
                float p = __expf(s[i][j] - mn);
                s[i][j] = p;
                ps += p;
            }
            #pragma unroll
            for (int off = 8; off > 0; off >>= 1)
                ps += __shfl_xor_sync(0xffffffffu, ps, off);
            lsum[i] = lsum[i] * corr + ps;
            #pragma unroll
            for (int j = 0; j < 4; j++) o[i][j] *= corr;
        }
        __syncthreads();   // everyone done reading K before overwriting with P

        #pragma unroll
        for (int i = 0; i < 4; i++)
            #pragma unroll
            for (int j = 0; j < 4; j++)
                KPs[(ty * 4 + i) * 65 + tx * 4 + j] = s[i][j];
        __syncthreads();

        // O += P V
        #pragma unroll 8
        for (int kc = 0; kc < 64; kc++) {
            float a[4], bv[4];
            #pragma unroll
            for (int i = 0; i < 4; i++) a[i]  = KPs[(ty * 4 + i) * 65 + kc];
            #pragma unroll
            for (int j = 0; j < 4; j++) bv[j] = Vs[kc * 65 + tx * 4 + j];
            #pragma unroll
            for (int i = 0; i < 4; i++)
                #pragma unroll
                for (int j = 0; j < 4; j++)
                    o[i][j] += a[i] * bv[j];
        }
        __syncthreads();   // before next tile load overwrites KPs/Vs
    }

    // epilogue: normalize, write y in [B, T, C] layout
    #pragma unroll
    for (int i = 0; i < 4; i++) {
        float inv = 1.f / lsum[i];
        int t = q0 + ty * 4 + i;
        #pragma unroll
        for (int j = 0; j < 4; j++)
            O[((size_t)b * TT + t) * CC + h * DH + tx * 4 + j] = o[i][j] * inv;
    }
}

// ---------------------------------------------------------------------------

extern "C" void kernel_launch(void* const* d_in, const int* in_sizes, int n_in,
                              void* d_out, int out_size) {
    const float* x  = (const float*)d_in[0];
    const float* Wq = (const float*)d_in[1];
    const float* bq = (const float*)d_in[2];
    const float* Wk = (const float*)d_in[3];
    const float* bk = (const float*)d_in[4];
    const float* Wv = (const float*)d_in[5];
    const float* bv = (const float*)d_in[6];
    const float* Wp = (const float*)d_in[7];
    const float* bp = (const float*)d_in[8];
    float* out = (float*)d_out;

    float *qp, *kp, *vp, *yp;
    cudaGetSymbolAddress((void**)&qp, g_q);
    cudaGetSymbolAddress((void**)&kp, g_k);
    cudaGetSymbolAddress((void**)&vp, g_v);
    cudaGetSymbolAddress((void**)&yp, g_y);

    dim3 blk(16, 16);
    dim3 g1(NN / 64, CC / 64);

    gemm_nt<true><<<g1, blk>>>(x, Wq, bq, qp);
    gemm_nt<true><<<g1, blk>>>(x, Wk, bk, kp);
    gemm_nt<true><<<g1, blk>>>(x, Wv, bv, vp);

    size_t smem = (size_t)3 * 64 * 65 * sizeof(float);  // 49920 B
    cudaFuncSetAttribute(flash_attn, cudaFuncAttributeMaxDynamicSharedMemorySize, (int)smem);
    flash_attn<<<dim3(TT / 64, BB * HH), blk, smem>>>(qp, kp, vp, yp);

    gemm_nt<false><<<g1, blk>>>(yp, Wp, bp, out);
}

// round 11
// speedup vs baseline: 2.8945x; 2.8945x over previous
#include <cuda_runtime.h>
#include <stdint.h>
#include <math.h>

#define BB 4
#define TT 2048
#define CC 768
#define HH 12
#define DH 64
#define NN (BB*TT)   // 8192 rows

__device__ float g_q[BB*HH*TT*DH];
__device__ float g_k[BB*HH*TT*DH];
__device__ float g_v[BB*HH*TT*DH];
__device__ float g_y[NN*CC];

#define NEG_INF (-1.0e30f)

// ---------------------------------------------------------------------------
// tf32 helpers
// ---------------------------------------------------------------------------
__device__ __forceinline__ uint32_t f2tf(float f) {
    uint32_t u;
    asm("cvt.rna.tf32.f32 %0, %1;" : "=r"(u) : "f"(f));
    return u;
}

// C(16x8,f32) += A(16x8,tf32,row) * B(8x8,tf32,col)
__device__ __forceinline__ void mma_tf32(float c[4],
                                         uint32_t a0, uint32_t a1, uint32_t a2, uint32_t a3,
                                         uint32_t b0, uint32_t b1) {
    asm volatile(
        "mma.sync.aligned.m16n8k8.row.col.f32.tf32.tf32.f32 "
        "{%0,%1,%2,%3}, {%4,%5,%6,%7}, {%8,%9}, {%0,%1,%2,%3};"
        : "+f"(c[0]), "+f"(c[1]), "+f"(c[2]), "+f"(c[3])
        : "r"(a0), "r"(a1), "r"(a2), "r"(a3), "r"(b0), "r"(b1));
}

// ---------------------------------------------------------------------------
// tf32 NT GEMM: out[n,o] = sum_c A[n,c]*W[o,c] + bias[o]
// BM=128, BN=64, BK=32. 256 threads = 8 warps (4 x 2).
// Warp tile 32x32 = 2 m16-tiles x 4 n8-tiles.
// smem stride 36 => frag LDS addr mod 32 = 4g+t4+const : conflict-free.
// ---------------------------------------------------------------------------
template<bool SPLIT>
__global__ void __launch_bounds__(256)
gemm_tf32(const float* __restrict__ A, const float* __restrict__ W,
          const float* __restrict__ bias, float* __restrict__ out) {
    __shared__ uint32_t As[128 * 36];
    __shared__ uint32_t Ws[64 * 36];

    const int tid  = threadIdx.x;
    const int lane = tid & 31;
    const int warp = tid >> 5;
    const int g    = lane >> 2;
    const int t4   = lane & 3;
    const int wm   = warp & 3;   // row group (32 rows)
    const int wn   = warp >> 2;  // col group (32 cols)

    const int n0 = blockIdx.x * 128;
    const int o0 = blockIdx.y * 64;

    float acc[2][4][4];
    #pragma unroll
    for (int mt = 0; mt < 2; mt++)
        #pragma unroll
        for (int nt = 0; nt < 4; nt++)
            #pragma unroll
            for (int i = 0; i < 4; i++) acc[mt][nt][i] = 0.f;

    const int lrow = tid >> 3;        // 0..31
    const int lc4  = (tid & 7) * 4;   // 0,4,...,28

    for (int k0 = 0; k0 < CC; k0 += 32) {
        #pragma unroll
        for (int it = 0; it < 4; it++) {
            int r = lrow + it * 32;
            float4 v = *(const float4*)&A[(size_t)(n0 + r) * CC + k0 + lc4];
            uint4 u = make_uint4(f2tf(v.x), f2tf(v.y), f2tf(v.z), f2tf(v.w));
            *(uint4*)&As[r * 36 + lc4] = u;
        }
        #pragma unroll
        for (int it = 0; it < 2; it++) {
            int r = lrow + it * 32;
            float4 v = *(const float4*)&W[(size_t)(o0 + r) * CC + k0 + lc4];
            uint4 u = make_uint4(f2tf(v.x), f2tf(v.y), f2tf(v.z), f2tf(v.w));
            *(uint4*)&Ws[r * 36 + lc4] = u;
        }
        __syncthreads();

        #pragma unroll
        for (int ks = 0; ks < 4; ks++) {
            uint32_t af[2][4];
            #pragma unroll
            for (int mt = 0; mt < 2; mt++) {
                int r = 32 * wm + 16 * mt + g;
                af[mt][0] = As[r * 36 + 8 * ks + t4];
                af[mt][1] = As[(r + 8) * 36 + 8 * ks + t4];
                af[mt][2] = As[r * 36 + 8 * ks + t4 + 4];
                af[mt][3] = As[(r + 8) * 36 + 8 * ks + t4 + 4];
            }
            #pragma unroll
            for (int nt = 0; nt < 4; nt++) {
                int r = 32 * wn + 8 * nt + g;
                uint32_t b0 = Ws[r * 36 + 8 * ks + t4];
                uint32_t b1 = Ws[r * 36 + 8 * ks + t4 + 4];
                #pragma unroll
                for (int mt = 0; mt < 2; mt++)
                    mma_tf32(acc[mt][nt], af[mt][0], af[mt][1], af[mt][2], af[mt][3], b0, b1);
            }
        }
        __syncthreads();
    }

    // epilogue
    #pragma unroll
    for (int mt = 0; mt < 2; mt++) {
        #pragma unroll
        for (int nt = 0; nt < 4; nt++) {
            int row = n0 + 32 * wm + 16 * mt + g;
            int col = o0 + 32 * wn + 8 * nt + 2 * t4;
            #pragma unroll
            for (int i = 0; i < 4; i++) {
                int n = row + (i >= 2 ? 8 : 0);
                int o = col + (i & 1);
                float v = acc[mt][nt][i] + bias[o];
                if (SPLIT) {
                    int b = n >> 11;
                    int t = n & (TT - 1);
                    int h = o >> 6;
                    int d = o & (DH - 1);
                    out[(((size_t)b * HH + h) * TT + t) * DH + d] = v;
                } else {
                    out[(size_t)n * CC + o] = v;
                }
            }
        }
    }
}

// ---------------------------------------------------------------------------
// Flash attention, tf32 mma, causal. Block = 128 threads (4 warps).
// Br=Bc=64, Dh=64. Warp w owns q-rows [16w, 16w+16).
// smem stride 68 (mod 32 == 4) => conflict-free A/B fragment loads for S.
// KPs holds K tile, then is overwritten with P tile.
// ---------------------------------------------------------------------------
__global__ void __launch_bounds__(128)
flash_tf32(const float* __restrict__ Q, const float* __restrict__ K,
           const float* __restrict__ V, float* __restrict__ O) {
    extern __shared__ uint32_t smu[];
    uint32_t* Qs  = smu;                 // 64*68
    uint32_t* KPs = smu + 64 * 68;       // K tile then P tile
    uint32_t* Vs  = smu + 2 * 64 * 68;

    const int tid  = threadIdx.x;
    const int lane = tid & 31;
    const int w    = tid >> 5;
    const int g    = lane >> 2;
    const int t4   = lane & 3;

    const int bh = blockIdx.y;
    const int b  = bh / HH;
    const int h  = bh - b * HH;
    const int q0 = blockIdx.x * 64;
    const size_t base = (size_t)bh * TT * DH;

    // load Q tile (convert to tf32)
    #pragma unroll
    for (int it = 0; it < 8; it++) {
        int idx = tid + it * 128;
        int r = idx >> 4, c4 = (idx & 15) * 4;
        float4 v = *(const float4*)&Q[base + (size_t)(q0 + r) * DH + c4];
        uint4 u = make_uint4(f2tf(v.x), f2tf(v.y), f2tf(v.z), f2tf(v.w));
        *(uint4*)&Qs[r * 68 + c4] = u;
    }

    float o[8][4];
    #pragma unroll
    for (int nt = 0; nt < 8; nt++)
        #pragma unroll
        for (int i = 0; i < 4; i++) o[nt][i] = 0.f;
    float m0 = NEG_INF, m1 = NEG_INF, l0 = 0.f, l1 = 0.f;
    const float scale = 0.125f;   // 1/sqrt(64)

    const int arow = 16 * w + g;
    const int ktiles = blockIdx.x + 1;

    for (int kt = 0; kt < ktiles; kt++) {
        const int k0 = kt * 64;
        // load K, V tiles
        #pragma unroll
        for (int it = 0; it < 8; it++) {
            int idx = tid + it * 128;
            int r = idx >> 4, c4 = (idx & 15) * 4;
            float4 kv = *(const float4*)&K[base + (size_t)(k0 + r) * DH + c4];
            float4 vv = *(const float4*)&V[base + (size_t)(k0 + r) * DH + c4];
            *(uint4*)&KPs[r * 68 + c4] = make_uint4(f2tf(kv.x), f2tf(kv.y), f2tf(kv.z), f2tf(kv.w));
            *(uint4*)&Vs[r * 68 + c4]  = make_uint4(f2tf(vv.x), f2tf(vv.y), f2tf(vv.z), f2tf(vv.w));
        }
        __syncthreads();

        // S = Q K^T  (16 rows per warp x 64 cols)
        float s[8][4];
        #pragma unroll
        for (int nt = 0; nt < 8; nt++)
            #pragma unroll
            for (int i = 0; i < 4; i++) s[nt][i] = 0.f;

        #pragma unroll
        for (int ks = 0; ks < 8; ks++) {
            uint32_t a0 = Qs[arow * 68 + 8 * ks + t4];
            uint32_t a1 = Qs[(arow + 8) * 68 + 8 * ks + t4];
            uint32_t a2 = Qs[arow * 68 + 8 * ks + t4 + 4];
            uint32_t a3 = Qs[(arow + 8) * 68 + 8 * ks + t4 + 4];
            #pragma unroll
            for (int nt = 0; nt < 8; nt++) {
                uint32_t b0 = KPs[(8 * nt + g) * 68 + 8 * ks + t4];
                uint32_t b1 = KPs[(8 * nt + g) * 68 + 8 * ks + t4 + 4];
                mma_tf32(s[nt], a0, a1, a2, a3, b0, b1);
            }
        }

        // scale + causal mask + online softmax
        const bool diag = (kt == blockIdx.x);
        const int qr0 = q0 + arow;
        const int qr1 = qr0 + 8;
        float rmax0 = NEG_INF, rmax1 = NEG_INF;
        #pragma unroll
        for (int nt = 0; nt < 8; nt++) {
            int c0 = k0 + 8 * nt + 2 * t4;
            int c1 = c0 + 1;
            float v0 = s[nt][0] * scale;
            float v1 = s[nt][1] * scale;
            float v2 = s[nt][2] * scale;
            float v3 = s[nt][3] * scale;
            if (diag) {
                if (c0 > qr0) v0 = NEG_INF;
                if (c1 > qr0) v1 = NEG_INF;
                if (c0 > qr1) v2 = NEG_INF;
                if (c1 > qr1) v3 = NEG_INF;
            }
            s[nt][0] = v0; s[nt][1] = v1; s[nt][2] = v2; s[nt][3] = v3;
            rmax0 = fmaxf(rmax0, fmaxf(v0, v1));
            rmax1 = fmaxf(rmax1, fmaxf(v2, v3));
        }
        #pragma unroll
        for (int off = 1; off <= 2; off <<= 1) {
            rmax0 = fmaxf(rmax0, __shfl_xor_sync(0xffffffffu, rmax0, off));
            rmax1 = fmaxf(rmax1, __shfl_xor_sync(0xffffffffu, rmax1, off));
        }
        float mn0 = fmaxf(m0, rmax0);
        float mn1 = fmaxf(m1, rmax1);
        float corr0 = __expf(m0 - mn0);
        float corr1 = __expf(m1 - mn1);
        m0 = mn0; m1 = mn1;

        float ps0 = 0.f, ps1 = 0.f;
        #pragma unroll
        for (int nt = 0; nt < 8; nt++) {
            float p0 = __expf(s[nt][0] - mn0);
            float p1 = __expf(s[nt][1] - mn0);
            float p2 = __expf(s[nt][2] - mn1);
            float p3 = __expf(s[nt][3] - mn1);
            s[nt][0] = p0; s[nt][1] = p1; s[nt][2] = p2; s[nt][3] = p3;
            ps0 += p0 + p1;
            ps1 += p2 + p3;
        }
        #pragma unroll
        for (int off = 1; off <= 2; off <<= 1) {
            ps0 += __shfl_xor_sync(0xffffffffu, ps0, off);
            ps1 += __shfl_xor_sync(0xffffffffu, ps1, off);
        }
        l0 = l0 * corr0 + ps0;
        l1 = l1 * corr1 + ps1;
        #pragma unroll
        for (int nt = 0; nt < 8; nt++) {
            o[nt][0] *= corr0; o[nt][1] *= corr0;
            o[nt][2] *= corr1; o[nt][3] *= corr1;
        }

        __syncthreads();   // all warps done reading K from KPs
        // write P (tf32) into KPs
        #pragma unroll
        for (int nt = 0; nt < 8; nt++) {
            int col = 8 * nt + 2 * t4;
            KPs[arow * 68 + col]           = f2tf(s[nt][0]);
            KPs[arow * 68 + col + 1]       = f2tf(s[nt][1]);
            KPs[(arow + 8) * 68 + col]     = f2tf(s[nt][2]);
            KPs[(arow + 8) * 68 + col + 1] = f2tf(s[nt][3]);
        }
        __syncthreads();

        // O += P V
        #pragma unroll
        for (int ks = 0; ks < 8; ks++) {
            uint32_t a0 = KPs[arow * 68 + 8 * ks + t4];
            uint32_t a1 = KPs[(arow + 8) * 68 + 8 * ks + t4];
            uint32_t a2 = KPs[arow * 68 + 8 * ks + t4 + 4];
            uint32_t a3 = KPs[(arow + 8) * 68 + 8 * ks + t4 + 4];
            #pragma unroll
            for (int nt = 0; nt < 8; nt++) {
                uint32_t b0 = Vs[(8 * ks + t4) * 68 + 8 * nt + g];
                uint32_t b1 = Vs[(8 * ks + t4 + 4) * 68 + 8 * nt + g];
                mma_tf32(o[nt], a0, a1, a2, a3, b0, b1);
            }
        }
        __syncthreads();   // before next tile load overwrites KPs/Vs
    }

    // epilogue: normalize, write y in [B, T, C] layout
    float inv0 = 1.f / l0;
    float inv1 = 1.f / l1;
    int t0 = q0 + arow;
    #pragma unroll
    for (int nt = 0; nt < 8; nt++) {
        int col = h * DH + 8 * nt + 2 * t4;
        size_t r0 = ((size_t)b * TT + t0) * CC + col;
        size_t r1 = ((size_t)b * TT + t0 + 8) * CC + col;
        O[r0]     = o[nt][0] * inv0;
        O[r0 + 1] = o[nt][1] * inv0;
        O[r1]     = o[nt][2] * inv1;
        O[r1 + 1] = o[nt][3] * inv1;
    }
}

// ---------------------------------------------------------------------------

extern "C" void kernel_launch(void* const* d_in, const int* in_sizes, int n_in,
                              void* d_out, int out_size) {
    const float* x  = (const float*)d_in[0];
    const float* Wq = (const float*)d_in[1];
    const float* bq = (const float*)d_in[2];
    const float* Wk = (const float*)d_in[3];
    const float* bk = (const float*)d_in[4];
    const float* Wv = (const float*)d_in[5];
    const float* bv = (const float*)d_in[6];
    const float* Wp = (const float*)d_in[7];
    const float* bp = (const float*)d_in[8];
    float* out = (float*)d_out;

    float *qp, *kp, *vp, *yp;
    cudaGetSymbolAddress((void**)&qp, g_q);
    cudaGetSymbolAddress((void**)&kp, g_k);
    cudaGetSymbolAddress((void**)&vp, g_v);
    cudaGetSymbolAddress((void**)&yp, g_y);

    dim3 g1(NN / 128, CC / 64);

    gemm_tf32<true><<<g1, 256>>>(x, Wq, bq, qp);
    gemm_tf32<true><<<g1, 256>>>(x, Wk, bk, kp);
    gemm_tf32<true><<<g1, 256>>>(x, Wv, bv, vp);

    size_t smem = (size_t)3 * 64 * 68 * sizeof(uint32_t);  // 52224 B
    cudaFuncSetAttribute(flash_tf32, cudaFuncAttributeMaxDynamicSharedMemorySize, (int)smem);
    flash_tf32<<<dim3(TT / 64, BB * HH), 128, smem>>>(qp, kp, vp, yp);

    gemm_tf32<false><<<g1, 256>>>(yp, Wp, bp, out);
}